// round 2
// baseline (speedup 1.0000x reference)
#include <cuda_runtime.h>
#include <math.h>

#define CLASS_PERIOD 360
#define MAX_B 16384
#define ROW_THREADS 128
#define VEC_PER_ROW (CLASS_PERIOD / 4)   // 90 float4 per row window

// Scratch for per-row partial sums (no device allocation allowed).
__device__ float g_partials[MAX_B];

// ---------------------------------------------------------------------------
// Kernel 1: one block per row. Gather the 360-wide window (90 float4s),
// compute sum_j l_j * log_softmax(p)_j deterministically, store partial.
// ---------------------------------------------------------------------------
__global__ __launch_bounds__(ROW_THREADS)
void vp_row_kernel(const float* __restrict__ preds,
                   const float* __restrict__ labels,
                   const int*   __restrict__ obj_classes,   // int32 (jax x64 off)
                   int W)
{
    const int row = blockIdx.x;
    const int tid = threadIdx.x;

    const long long base = (long long)row * (long long)W
                         + (long long)obj_classes[row] * CLASS_PERIOD;
    // base is a multiple of 4 floats (360*c) on a 16B-aligned row -> float4-safe
    const float4* __restrict__ p4 = (const float4*)(preds  + base);
    const float4* __restrict__ l4 = (const float4*)(labels + base);

    const bool active = (tid < VEC_PER_ROW);
    float4 pv = make_float4(0.f, 0.f, 0.f, 0.f);
    float4 lv = make_float4(0.f, 0.f, 0.f, 0.f);
    float local_max = -INFINITY;
    if (active) {
        pv = p4[tid];
        lv = l4[tid];
        local_max = fmaxf(fmaxf(pv.x, pv.y), fmaxf(pv.z, pv.w));
    }

    const int lane = tid & 31;
    const int warp = tid >> 5;
    __shared__ float s_red[ROW_THREADS / 32];

    // ---- block max ----
    #pragma unroll
    for (int off = 16; off > 0; off >>= 1)
        local_max = fmaxf(local_max, __shfl_xor_sync(0xFFFFFFFFu, local_max, off));
    if (lane == 0) s_red[warp] = local_max;
    __syncthreads();
    float m = fmaxf(fmaxf(s_red[0], s_red[1]), fmaxf(s_red[2], s_red[3]));

    // ---- local sums: expsum, dot = sum l*(p-m), lsum ----
    float es = 0.0f, dt = 0.0f, ls = 0.0f;
    if (active) {
        float d0 = pv.x - m, d1 = pv.y - m, d2 = pv.z - m, d3 = pv.w - m;
        es = __expf(d0) + __expf(d1) + __expf(d2) + __expf(d3);
        dt = lv.x * d0 + lv.y * d1 + lv.z * d2 + lv.w * d3;
        ls = lv.x + lv.y + lv.z + lv.w;
    }

    // ---- block sum of (es, dt, ls) ----
    #pragma unroll
    for (int off = 16; off > 0; off >>= 1) {
        es += __shfl_xor_sync(0xFFFFFFFFu, es, off);
        dt += __shfl_xor_sync(0xFFFFFFFFu, dt, off);
        ls += __shfl_xor_sync(0xFFFFFFFFu, ls, off);
    }
    __shared__ float s_es[ROW_THREADS / 32];
    __shared__ float s_dt[ROW_THREADS / 32];
    __shared__ float s_ls[ROW_THREADS / 32];
    __syncthreads();
    if (lane == 0) { s_es[warp] = es; s_dt[warp] = dt; s_ls[warp] = ls; }
    __syncthreads();

    if (tid == 0) {
        float tes = s_es[0] + s_es[1] + s_es[2] + s_es[3];
        float tdt = s_dt[0] + s_dt[1] + s_dt[2] + s_dt[3];
        float tls = s_ls[0] + s_ls[1] + s_ls[2] + s_ls[3];
        // sum_j l_j * (p_j - m - log(sum exp)) = tdt - log(tes)*tls
        g_partials[row] = tdt - logf(tes) * tls;
    }
}

// ---------------------------------------------------------------------------
// Kernel 2: single block reduces the per-row partials deterministically.
// ---------------------------------------------------------------------------
#define RED_THREADS 512

__global__ __launch_bounds__(RED_THREADS)
void vp_reduce_kernel(float* __restrict__ out, int B)
{
    const int tid = threadIdx.x;
    float acc = 0.0f;
    for (int i = tid; i < B; i += RED_THREADS)
        acc += g_partials[i];

    __shared__ float s[RED_THREADS / 32];
    const int lane = tid & 31;
    const int warp = tid >> 5;
    #pragma unroll
    for (int off = 16; off > 0; off >>= 1)
        acc += __shfl_xor_sync(0xFFFFFFFFu, acc, off);
    if (lane == 0) s[warp] = acc;
    __syncthreads();
    if (tid == 0) {
        float tot = 0.0f;
        #pragma unroll
        for (int w = 0; w < RED_THREADS / 32; w++) tot += s[w];
        out[0] = -tot / ((float)CLASS_PERIOD * (float)B);
    }
}

// ---------------------------------------------------------------------------
extern "C" void kernel_launch(void* const* d_in, const int* in_sizes, int n_in,
                              void* d_out, int out_size)
{
    const float* preds  = (const float*)d_in[0];
    const float* labels = (const float*)d_in[1];
    const int*   objcls = (const int*)d_in[2];

    const int B = in_sizes[2];               // 16384
    const int W = in_sizes[0] / B;           // 4320

    vp_row_kernel<<<B, ROW_THREADS>>>(preds, labels, objcls, W);
    vp_reduce_kernel<<<1, RED_THREADS>>>((float*)d_out, B);
}

// round 3
// speedup vs baseline: 1.4837x; 1.4837x over previous
#include <cuda_runtime.h>
#include <math.h>

#define CLASS_PERIOD 360
#define VEC_PER_ROW  (CLASS_PERIOD / 4)    // 90 float4 per window
#define ROWS_PER_BLOCK 8
#define BLOCK_THREADS  (ROWS_PER_BLOCK * 32)
#define MAX_BLOCKS 4096

// Scratch (no device allocation allowed): per-block partials + ticket counter.
__device__ float        g_block_partials[MAX_BLOCKS];
__device__ unsigned int g_ticket = 0;

// ---------------------------------------------------------------------------
// Single fused kernel: one warp per row. Warp gathers the 90-float4 window,
// computes sum_j l_j * log_softmax(p)_j via warp shuffles, block sums its
// 8 row-partials in fixed order, last finished block reduces all partials.
// ---------------------------------------------------------------------------
__global__ __launch_bounds__(BLOCK_THREADS)
void vp_fused_kernel(const float* __restrict__ preds,
                     const float* __restrict__ labels,
                     const int*   __restrict__ obj_classes,  // int32
                     float* __restrict__ out,
                     int W, int B)
{
    const int tid  = threadIdx.x;
    const int lane = tid & 31;
    const int warp = tid >> 5;
    const int row  = blockIdx.x * ROWS_PER_BLOCK + warp;

    const int nblocks = gridDim.x;

    // ---------------- per-warp row computation ----------------
    const long long base = (long long)row * (long long)W
                         + (long long)obj_classes[row] * CLASS_PERIOD;
    const float4* __restrict__ p4 = (const float4*)(preds  + base);
    const float4* __restrict__ l4 = (const float4*)(labels + base);

    // lane, lane+32, lane+64 ; third chunk active only for lane < 26
    float4 pv0 = p4[lane];
    float4 pv1 = p4[lane + 32];
    float4 lv0 = l4[lane];
    float4 lv1 = l4[lane + 32];
    const bool a2 = (lane + 64) < VEC_PER_ROW;
    float4 pv2 = make_float4(0.f, 0.f, 0.f, 0.f);
    float4 lv2 = make_float4(0.f, 0.f, 0.f, 0.f);
    if (a2) { pv2 = p4[lane + 64]; lv2 = l4[lane + 64]; }

    float mx = fmaxf(fmaxf(pv0.x, pv0.y), fmaxf(pv0.z, pv0.w));
    mx = fmaxf(mx, fmaxf(fmaxf(pv1.x, pv1.y), fmaxf(pv1.z, pv1.w)));
    if (a2) mx = fmaxf(mx, fmaxf(fmaxf(pv2.x, pv2.y), fmaxf(pv2.z, pv2.w)));

    #pragma unroll
    for (int off = 16; off > 0; off >>= 1)
        mx = fmaxf(mx, __shfl_xor_sync(0xFFFFFFFFu, mx, off));

    // local sums: expsum, dot = sum l*(p-m), lsum
    float es, dt, ls;
    {
        float d0 = pv0.x - mx, d1 = pv0.y - mx, d2 = pv0.z - mx, d3 = pv0.w - mx;
        float e0 = pv1.x - mx, e1 = pv1.y - mx, e2 = pv1.z - mx, e3 = pv1.w - mx;
        es = __expf(d0) + __expf(d1) + __expf(d2) + __expf(d3)
           + __expf(e0) + __expf(e1) + __expf(e2) + __expf(e3);
        dt = lv0.x * d0 + lv0.y * d1 + lv0.z * d2 + lv0.w * d3
           + lv1.x * e0 + lv1.y * e1 + lv1.z * e2 + lv1.w * e3;
        ls = lv0.x + lv0.y + lv0.z + lv0.w
           + lv1.x + lv1.y + lv1.z + lv1.w;
        if (a2) {
            float f0 = pv2.x - mx, f1 = pv2.y - mx, f2 = pv2.z - mx, f3 = pv2.w - mx;
            es += __expf(f0) + __expf(f1) + __expf(f2) + __expf(f3);
            dt += lv2.x * f0 + lv2.y * f1 + lv2.z * f2 + lv2.w * f3;
            ls += lv2.x + lv2.y + lv2.z + lv2.w;
        }
    }

    #pragma unroll
    for (int off = 16; off > 0; off >>= 1) {
        es += __shfl_xor_sync(0xFFFFFFFFu, es, off);
        dt += __shfl_xor_sync(0xFFFFFFFFu, dt, off);
        ls += __shfl_xor_sync(0xFFFFFFFFu, ls, off);
    }

    // ---------------- block partial (fixed order -> deterministic) --------
    __shared__ float s_row[ROWS_PER_BLOCK];
    if (lane == 0)
        s_row[warp] = dt - logf(es) * ls;   // sum_j l_j * log_softmax(p)_j
    __syncthreads();

    __shared__ bool s_is_last;
    if (tid == 0) {
        float bp = 0.0f;
        #pragma unroll
        for (int w = 0; w < ROWS_PER_BLOCK; w++) bp += s_row[w];
        g_block_partials[blockIdx.x] = bp;
        __threadfence();
        unsigned int t = atomicAdd(&g_ticket, 1u);
        s_is_last = (t == (unsigned)(nblocks - 1));
    }
    __syncthreads();

    // ---------------- last block: final reduce ----------------------------
    if (s_is_last) {
        float acc = 0.0f;
        for (int i = tid; i < nblocks; i += BLOCK_THREADS)
            acc += g_block_partials[i];

        #pragma unroll
        for (int off = 16; off > 0; off >>= 1)
            acc += __shfl_xor_sync(0xFFFFFFFFu, acc, off);

        __shared__ float s_fin[BLOCK_THREADS / 32];
        if (lane == 0) s_fin[warp] = acc;
        __syncthreads();
        if (tid == 0) {
            float tot = 0.0f;
            #pragma unroll
            for (int w = 0; w < BLOCK_THREADS / 32; w++) tot += s_fin[w];
            out[0] = -tot / ((float)CLASS_PERIOD * (float)B);
            g_ticket = 0;   // reset for next graph replay (all increments done)
        }
    }
}

// ---------------------------------------------------------------------------
extern "C" void kernel_launch(void* const* d_in, const int* in_sizes, int n_in,
                              void* d_out, int out_size)
{
    const float* preds  = (const float*)d_in[0];
    const float* labels = (const float*)d_in[1];
    const int*   objcls = (const int*)d_in[2];

    const int B = in_sizes[2];               // 16384
    const int W = in_sizes[0] / B;           // 4320
    const int nblocks = B / ROWS_PER_BLOCK;  // 2048

    vp_fused_kernel<<<nblocks, BLOCK_THREADS>>>(preds, labels, objcls,
                                                (float*)d_out, W, B);
}